// round 11
// baseline (speedup 1.0000x reference)
#include <cuda_runtime.h>
#include <math.h>

// ---------------- problem dims ----------------
#define BSZ 256
#define TT  128
#define FF  512
#define HH  1024
#define G4  4096

// ---------------- scratch (device globals) ----------------
__device__ float g_xproj[(size_t)BSZ * TT * G4]; // [B*T, 4H]
__device__ float g_gbuf[BSZ * G4];               // per-step gates
__device__ float g_pf[BSZ * HH];
__device__ float g_pi[BSZ * HH];
__device__ float g_h[BSZ * HH];
__device__ float g_c[BSZ * HH];

__device__ __forceinline__ float sigm(float v) { return 1.0f / (1.0f + expf(-v)); }
__device__ __forceinline__ float lo32(unsigned long long v) {
    return __uint_as_float((unsigned)(v & 0xffffffffull));
}
__device__ __forceinline__ float hi32(unsigned long long v) {
    return __uint_as_float((unsigned)(v >> 32));
}

// packed dual-FMA: {c.lo,c.hi} += {a.lo,a.hi} * {b.lo,b.hi}   (IEEE fp32 per lane)
#define FMA2(c, a, b) \
    asm("fma.rn.f32x2 %0, %1, %2, %0;" : "+l"(c) : "l"(a), "l"(b));

// ---------------- 64x64 tile GEMM core (f32x2), Round-2 skeleton ------------
// C(64x64) = A[m0.., :K] * B[:K, n0..]; A row-major [M,lda], B row-major [K,ldb].
// 256 threads; thread (tx,ty) owns rows ty*4..+3, cols tx*4..+3.
// sA: [k][64] (A transposed, m-contiguous -> natural {a_i,a_i+1} pairs)
// sBd:[k][128] (B duplicated: col j stored at 2j,2j+1 -> natural {b_j,b_j} pairs)
// Accumulators: 8 packed b64: cPQ = {C[2P+0][Q], C[2P+1][Q]} rel. to (ty*4, tx*4).
#define GEMM_SMEM() \
    __shared__ float sA[16 * 64]; \
    __shared__ float sBd[16 * 128]; \
    const int tid  = threadIdx.x; \
    const int tx   = tid & 15; \
    const int ty   = tid >> 4; \
    const int arow = tid >> 2; \
    const int acol = (tid & 3) * 4; \
    const int brow = tid >> 4; \
    const int bcol = (tid & 15) * 4; \
    unsigned long long c00 = 0ull, c01 = 0ull, c02 = 0ull, c03 = 0ull; \
    unsigned long long c10 = 0ull, c11 = 0ull, c12 = 0ull, c13 = 0ull;

#define GEMM_CORE(Aptr, lda, Bptr, ldb, Kdim) \
    for (int kc = 0; kc < (Kdim) / 16; kc++) { \
        const int kb = kc * 16; \
        __syncthreads(); \
        { \
            float4 av = *(const float4*)&(Aptr)[(size_t)(m0 + arow) * (lda) + kb + acol]; \
            sA[(acol + 0) * 64 + arow] = av.x; \
            sA[(acol + 1) * 64 + arow] = av.y; \
            sA[(acol + 2) * 64 + arow] = av.z; \
            sA[(acol + 3) * 64 + arow] = av.w; \
            float4 bv = *(const float4*)&(Bptr)[(size_t)(kb + brow) * (ldb) + n0 + bcol]; \
            *(float4*)&sBd[brow * 128 + bcol * 2]     = make_float4(bv.x, bv.x, bv.y, bv.y); \
            *(float4*)&sBd[brow * 128 + bcol * 2 + 4] = make_float4(bv.z, bv.z, bv.w, bv.w); \
        } \
        __syncthreads(); \
        _Pragma("unroll") \
        for (int k = 0; k < 16; k++) { \
            ulonglong2 aa  = *(const ulonglong2*)&sA[k * 64 + ty * 4]; \
            ulonglong2 bb0 = *(const ulonglong2*)&sBd[k * 128 + tx * 8]; \
            ulonglong2 bb1 = *(const ulonglong2*)&sBd[k * 128 + tx * 8 + 4]; \
            FMA2(c00, aa.x, bb0.x) FMA2(c01, aa.x, bb0.y) \
            FMA2(c02, aa.x, bb1.x) FMA2(c03, aa.x, bb1.y) \
            FMA2(c10, aa.y, bb0.x) FMA2(c11, aa.y, bb0.y) \
            FMA2(c12, aa.y, bb1.x) FMA2(c13, aa.y, bb1.y) \
        } \
    }

// per-thread result rows (relative): r+0: lo(c0q), r+1: hi(c0q), r+2: lo(c1q), r+3: hi(c1q)
#define ACC_ROW0(q) lo32(c0##q)
#define ACC_ROW1(q) hi32(c0##q)
#define ACC_ROW2(q) lo32(c1##q)
#define ACC_ROW3(q) hi32(c1##q)

// ---------------- kernels ---------------------------------------------------
__global__ void k_init()
{
    int idx = blockIdx.x * blockDim.x + threadIdx.x;
    if (idx < BSZ * HH) { g_h[idx] = 0.0f; g_c[idx] = 0.0f; }
}

// x_proj = x @ W_x + b    (M=32768, K=512, N=4096); grid (64, 512)
__global__ void k_xproj(const float* __restrict__ x,
                        const float* __restrict__ Wx,
                        const float* __restrict__ bias)
{
    const int m0 = blockIdx.y * 64, n0 = blockIdx.x * 64;
    GEMM_SMEM();
    GEMM_CORE(x, FF, Wx, G4, FF);

    const int cc = n0 + tx * 4;
    float4 bb = *(const float4*)&bias[cc];
    {
        size_t r = (size_t)m0 + ty * 4;
        *(float4*)&g_xproj[(r + 0) * G4 + cc] = make_float4(
            ACC_ROW0(0) + bb.x, ACC_ROW0(1) + bb.y, ACC_ROW0(2) + bb.z, ACC_ROW0(3) + bb.w);
        *(float4*)&g_xproj[(r + 1) * G4 + cc] = make_float4(
            ACC_ROW1(0) + bb.x, ACC_ROW1(1) + bb.y, ACC_ROW1(2) + bb.z, ACC_ROW1(3) + bb.w);
        *(float4*)&g_xproj[(r + 2) * G4 + cc] = make_float4(
            ACC_ROW2(0) + bb.x, ACC_ROW2(1) + bb.y, ACC_ROW2(2) + bb.z, ACC_ROW2(3) + bb.w);
        *(float4*)&g_xproj[(r + 3) * G4 + cc] = make_float4(
            ACC_ROW3(0) + bb.x, ACC_ROW3(1) + bb.y, ACC_ROW3(2) + bb.z, ACC_ROW3(3) + bb.w);
    }
}

// phase A: z0: gbuf = xp_t + h@R_h (N=4096); z1: pf = c@P_f; z2: pi = c@P_i (N=1024)
// grid (64, 4, 3)
__global__ void k_phaseA(const float* __restrict__ Rh,
                         const float* __restrict__ Pf,
                         const float* __restrict__ Pi,
                         int t)
{
    const int z = blockIdx.z;
    if (z > 0 && blockIdx.x >= 16) return;

    const int m0 = blockIdx.y * 64, n0 = blockIdx.x * 64;
    GEMM_SMEM();

    if (z == 0)      { GEMM_CORE(g_h, HH, Rh, G4, HH); }
    else if (z == 1) { GEMM_CORE(g_c, HH, Pf, HH, HH); }
    else             { GEMM_CORE(g_c, HH, Pi, HH, HH); }

    const int cc = n0 + tx * 4;
    size_t r = (size_t)m0 + ty * 4;
    if (z == 0) {
#define WR_G(i, R0, R1, R2, R3) { \
        float4 xp = *(const float4*)&g_xproj[((r + i) * TT + t) * (size_t)G4 + cc]; \
        *(float4*)&g_gbuf[(r + i) * G4 + cc] = \
            make_float4(R0 + xp.x, R1 + xp.y, R2 + xp.z, R3 + xp.w); }
        WR_G(0, ACC_ROW0(0), ACC_ROW0(1), ACC_ROW0(2), ACC_ROW0(3))
        WR_G(1, ACC_ROW1(0), ACC_ROW1(1), ACC_ROW1(2), ACC_ROW1(3))
        WR_G(2, ACC_ROW2(0), ACC_ROW2(1), ACC_ROW2(2), ACC_ROW2(3))
        WR_G(3, ACC_ROW3(0), ACC_ROW3(1), ACC_ROW3(2), ACC_ROW3(3))
#undef WR_G
    } else {
        float* outp = (z == 1) ? g_pf : g_pi;
        *(float4*)&outp[(r + 0) * HH + cc] =
            make_float4(ACC_ROW0(0), ACC_ROW0(1), ACC_ROW0(2), ACC_ROW0(3));
        *(float4*)&outp[(r + 1) * HH + cc] =
            make_float4(ACC_ROW1(0), ACC_ROW1(1), ACC_ROW1(2), ACC_ROW1(3));
        *(float4*)&outp[(r + 2) * HH + cc] =
            make_float4(ACC_ROW2(0), ACC_ROW2(1), ACC_ROW2(2), ACC_ROW2(3));
        *(float4*)&outp[(r + 3) * HH + cc] =
            make_float4(ACC_ROW3(0), ACC_ROW3(1), ACC_ROW3(2), ACC_ROW3(3));
    }
}

// cell update
__global__ void k_cell()
{
    int idx = blockIdx.x * blockDim.x + threadIdx.x;
    if (idx >= BSZ * HH) return;
    int b = idx >> 10, j = idx & 1023;
    const float* gr = g_gbuf + (size_t)b * G4;
    float f = sigm(gr[j] + g_pf[idx]);
    float i = sigm(gr[HH + j] + g_pi[idx]);
    float ct = tanhf(gr[2 * HH + j]);
    g_c[idx] = g_c[idx] * f + ct * i;
}

// phase B: po = c@P_o ; h = tanh(c) * sigm(go + po) ; grid (16, 4)
__global__ void k_phaseB(const float* __restrict__ Po,
                         float* __restrict__ dout, int last)
{
    const int m0 = blockIdx.y * 64, n0 = blockIdx.x * 64;
    GEMM_SMEM();
    GEMM_CORE(g_c, HH, Po, HH, HH);

    const int cc = n0 + tx * 4;
    size_t r = (size_t)m0 + ty * 4;
#define WR_H(i, R0, R1, R2, R3) { \
    float4 cv = *(const float4*)&g_c[(r + i) * HH + cc]; \
    float4 ov = *(const float4*)&g_gbuf[(r + i) * G4 + 3 * HH + cc]; \
    float4 v; \
    v.x = tanhf(cv.x) * sigm(ov.x + R0); \
    v.y = tanhf(cv.y) * sigm(ov.y + R1); \
    v.z = tanhf(cv.z) * sigm(ov.z + R2); \
    v.w = tanhf(cv.w) * sigm(ov.w + R3); \
    *(float4*)&g_h[(r + i) * HH + cc] = v; \
    if (last) *(float4*)&dout[(r + i) * HH + cc] = v; }
    WR_H(0, ACC_ROW0(0), ACC_ROW0(1), ACC_ROW0(2), ACC_ROW0(3))
    WR_H(1, ACC_ROW1(0), ACC_ROW1(1), ACC_ROW1(2), ACC_ROW1(3))
    WR_H(2, ACC_ROW2(0), ACC_ROW2(1), ACC_ROW2(2), ACC_ROW2(3))
    WR_H(3, ACC_ROW3(0), ACC_ROW3(1), ACC_ROW3(2), ACC_ROW3(3))
#undef WR_H
}

// ---------------- launch -----------------------------------------------------
extern "C" void kernel_launch(void* const* d_in, const int* in_sizes, int n_in,
                              void* d_out, int out_size)
{
    const float* x  = (const float*)d_in[0];
    const float* Wx = (const float*)d_in[1];
    const float* b  = (const float*)d_in[2];
    const float* Rh = (const float*)d_in[3];
    const float* Pf = (const float*)d_in[4];
    const float* Pi = (const float*)d_in[5];
    const float* Po = (const float*)d_in[6];
    float* out = (float*)d_out;
    (void)in_sizes; (void)n_in; (void)out_size;

    const int nElem = BSZ * HH;
    k_init<<<(nElem + 511) / 512, 512>>>();

    k_xproj<<<dim3(G4 / 64, (BSZ * TT) / 64), 256>>>(x, Wx, b);

    for (int t = 0; t < TT; t++) {
        k_phaseA<<<dim3(G4 / 64, BSZ / 64, 3), 256>>>(Rh, Pf, Pi, t);
        k_cell<<<(nElem + 511) / 512, 512>>>();
        k_phaseB<<<dim3(HH / 64, BSZ / 64), 256>>>(Po, out, (t == TT - 1) ? 1 : 0);
    }
}

// round 12
// speedup vs baseline: 2.6641x; 2.6641x over previous
#include <cuda_runtime.h>
#include <math.h>

// ---------------- problem dims ----------------
#define BSZ 256
#define TT  128
#define FF  512
#define HH  1024
#define G4  4096

#define SAP 68   // sA row pitch (64 + 4): 272B rows -> 16B-aligned float4 reads

// ---------------- scratch (device globals) ----------------
__device__ float g_xproj[(size_t)BSZ * TT * G4]; // [B*T, 4H]
__device__ float g_gbuf[BSZ * G4];               // per-step gates
__device__ float g_pf[BSZ * HH];                 // c_{t-1} @ P_f (made by prev phaseB)
__device__ float g_pi[BSZ * HH];                 // c_{t-1} @ P_i
__device__ float g_h[BSZ * HH];
__device__ float g_c[BSZ * HH];

__device__ __forceinline__ float sigm(float v) { return 1.0f / (1.0f + expf(-v)); }

// ---------------- 64x64 GEMM core: reg-staged double buffer, 1 sync/chunk ---
// C(64x64) = A[m0.., :K] * B[:K, n0..]; A row-major [M,lda], B row-major [K,ldb].
// 256 threads; thread (tx,ty) owns rows ty*4..+3, cols tx*4..+3.
// sA: [buf][k][64+pad] (k-major), sB: [buf][k][64].
__device__ __forceinline__ void gemm_core(
    const float* __restrict__ A, int lda,
    const float* __restrict__ B, int ldb,
    int K, int m0, int n0,
    float* sA, float* sB, float acc[4][4])
{
    const int tid  = threadIdx.x;
    const int tx   = tid & 15;
    const int ty   = tid >> 4;
    const int arow = tid >> 2;         // 0..63
    const int acol = (tid & 3) * 4;    // k offset 0,4,8,12
    const int brow = tid >> 4;         // 0..15
    const int bcol = (tid & 15) * 4;   // 0..60

    const int nkc = K / 16;

    // preload chunk 0 -> regs -> buffer 0
    float4 ra = *(const float4*)&A[(size_t)(m0 + arow) * lda + acol];
    float4 rb = *(const float4*)&B[(size_t)brow * ldb + n0 + bcol];
    sA[(acol + 0) * SAP + arow] = ra.x;
    sA[(acol + 1) * SAP + arow] = ra.y;
    sA[(acol + 2) * SAP + arow] = ra.z;
    sA[(acol + 3) * SAP + arow] = ra.w;
    *(float4*)&sB[brow * 64 + bcol] = rb;
    __syncthreads();

    for (int kc = 0; kc < nkc; kc++) {
        const float* bufA = sA + (kc & 1) * (16 * SAP);
        const float* bufB = sB + (kc & 1) * (16 * 64);
        const bool more = (kc + 1 < nkc);

        // issue next chunk's loads into registers (no dependent consumer yet)
        if (more) {
            const int kb = (kc + 1) * 16;
            ra = *(const float4*)&A[(size_t)(m0 + arow) * lda + kb + acol];
            rb = *(const float4*)&B[(size_t)(kb + brow) * ldb + n0 + bcol];
        }

        // compute on current buffer (overlaps in-flight LDGs)
#pragma unroll
        for (int k = 0; k < 16; k++) {
            float4 aa = *(const float4*)&bufA[k * SAP + ty * 4];
            float4 bb = *(const float4*)&bufB[k * 64 + tx * 4];
            acc[0][0] += aa.x * bb.x; acc[0][1] += aa.x * bb.y; acc[0][2] += aa.x * bb.z; acc[0][3] += aa.x * bb.w;
            acc[1][0] += aa.y * bb.x; acc[1][1] += aa.y * bb.y; acc[1][2] += aa.y * bb.z; acc[1][3] += aa.y * bb.w;
            acc[2][0] += aa.z * bb.x; acc[2][1] += aa.z * bb.y; acc[2][2] += aa.z * bb.z; acc[2][3] += aa.z * bb.w;
            acc[3][0] += aa.w * bb.x; acc[3][1] += aa.w * bb.y; acc[3][2] += aa.w * bb.z; acc[3][3] += aa.w * bb.w;
        }

        // stage regs into the other buffer; one sync ends the chunk
        if (more) {
            float* nA = sA + ((kc & 1) ^ 1) * (16 * SAP);
            float* nB = sB + ((kc & 1) ^ 1) * (16 * 64);
            nA[(acol + 0) * SAP + arow] = ra.x;
            nA[(acol + 1) * SAP + arow] = ra.y;
            nA[(acol + 2) * SAP + arow] = ra.z;
            nA[(acol + 3) * SAP + arow] = ra.w;
            *(float4*)&nB[brow * 64 + bcol] = rb;
            __syncthreads();
        }
    }
}

#define GEMM_SMEM() \
    __shared__ float sA[2 * 16 * SAP]; \
    __shared__ float sB[2 * 16 * 64]; \
    float acc[4][4] = {}; \
    const int tx = threadIdx.x & 15; \
    const int ty = threadIdx.x >> 4;

// ---------------- kernels ---------------------------------------------------
__global__ void k_init()
{
    int idx = blockIdx.x * blockDim.x + threadIdx.x;
    if (idx < BSZ * HH) {
        g_h[idx] = 0.0f; g_c[idx] = 0.0f;
        g_pf[idx] = 0.0f; g_pi[idx] = 0.0f;   // c_{-1} @ P = 0
    }
}

// x_proj = x @ W_x + b    (M=32768, K=512, N=4096); grid (64, 512)
__global__ void k_xproj(const float* __restrict__ x,
                        const float* __restrict__ Wx,
                        const float* __restrict__ bias)
{
    const int m0 = blockIdx.y * 64, n0 = blockIdx.x * 64;
    GEMM_SMEM();
    gemm_core(x, FF, Wx, G4, FF, m0, n0, sA, sB, acc);

    const int cc = n0 + tx * 4;
    float4 bb = *(const float4*)&bias[cc];
#pragma unroll
    for (int i = 0; i < 4; i++) {
        size_t row = (size_t)m0 + ty * 4 + i;
        float4 v = make_float4(acc[i][0] + bb.x, acc[i][1] + bb.y,
                               acc[i][2] + bb.z, acc[i][3] + bb.w);
        *(float4*)&g_xproj[row * G4 + cc] = v;
    }
}

// phase A: gbuf = xp_t + h @ R_h   (N=4096); grid (64, 4)
__global__ void k_phaseA(const float* __restrict__ Rh, int t)
{
    const int m0 = blockIdx.y * 64, n0 = blockIdx.x * 64;
    GEMM_SMEM();
    gemm_core(g_h, HH, Rh, G4, HH, m0, n0, sA, sB, acc);

    const int cc = n0 + tx * 4;
#pragma unroll
    for (int i = 0; i < 4; i++) {
        size_t row = (size_t)m0 + ty * 4 + i;
        float4 xp = *(const float4*)&g_xproj[(row * TT + t) * (size_t)G4 + cc];
        float4 v = make_float4(acc[i][0] + xp.x, acc[i][1] + xp.y,
                               acc[i][2] + xp.z, acc[i][3] + xp.w);
        *(float4*)&g_gbuf[row * G4 + cc] = v;
    }
}

// cell update: uses pf/pi = c_{t-1} @ P_f/P_i (written by previous phaseB)
__global__ void k_cell()
{
    int idx = blockIdx.x * blockDim.x + threadIdx.x;
    if (idx >= BSZ * HH) return;
    int b = idx >> 10, j = idx & 1023;
    const float* gr = g_gbuf + (size_t)b * G4;
    float f = sigm(gr[j] + g_pf[idx]);
    float i = sigm(gr[HH + j] + g_pi[idx]);
    float ct = tanhf(gr[2 * HH + j]);
    g_c[idx] = g_c[idx] * f + ct * i;
}

// phase B (3 jobs, all A = c_t):  z0: h = tanh(c)*sigm(go + c@P_o)
//                                 z1: g_pf = c@P_f (for step t+1)
//                                 z2: g_pi = c@P_i (for step t+1)
// grid (16, 4, 3)
__global__ void k_phaseB(const float* __restrict__ Po,
                         const float* __restrict__ Pf,
                         const float* __restrict__ Pi,
                         float* __restrict__ dout, int last)
{
    const int z = blockIdx.z;
    const int m0 = blockIdx.y * 64, n0 = blockIdx.x * 64;
    GEMM_SMEM();

    if (z == 0)      gemm_core(g_c, HH, Po, HH, HH, m0, n0, sA, sB, acc);
    else if (z == 1) gemm_core(g_c, HH, Pf, HH, HH, m0, n0, sA, sB, acc);
    else             gemm_core(g_c, HH, Pi, HH, HH, m0, n0, sA, sB, acc);

    const int cc = n0 + tx * 4;
    if (z == 0) {
#pragma unroll
        for (int i = 0; i < 4; i++) {
            size_t row = (size_t)m0 + ty * 4 + i;
            float4 cv = *(const float4*)&g_c[row * HH + cc];
            float4 ov = *(const float4*)&g_gbuf[row * G4 + 3 * HH + cc];
            float4 v;
            v.x = tanhf(cv.x) * sigm(ov.x + acc[i][0]);
            v.y = tanhf(cv.y) * sigm(ov.y + acc[i][1]);
            v.z = tanhf(cv.z) * sigm(ov.z + acc[i][2]);
            v.w = tanhf(cv.w) * sigm(ov.w + acc[i][3]);
            *(float4*)&g_h[row * HH + cc] = v;
            if (last) *(float4*)&dout[row * HH + cc] = v;
        }
    } else {
        float* outp = (z == 1) ? g_pf : g_pi;
#pragma unroll
        for (int i = 0; i < 4; i++) {
            size_t row = (size_t)m0 + ty * 4 + i;
            float4 v = make_float4(acc[i][0], acc[i][1], acc[i][2], acc[i][3]);
            *(float4*)&outp[row * HH + cc] = v;
        }
    }
}

// ---------------- launch -----------------------------------------------------
extern "C" void kernel_launch(void* const* d_in, const int* in_sizes, int n_in,
                              void* d_out, int out_size)
{
    const float* x  = (const float*)d_in[0];
    const float* Wx = (const float*)d_in[1];
    const float* b  = (const float*)d_in[2];
    const float* Rh = (const float*)d_in[3];
    const float* Pf = (const float*)d_in[4];
    const float* Pi = (const float*)d_in[5];
    const float* Po = (const float*)d_in[6];
    float* out = (float*)d_out;
    (void)in_sizes; (void)n_in; (void)out_size;

    const int nElem = BSZ * HH;
    k_init<<<(nElem + 511) / 512, 512>>>();

    k_xproj<<<dim3(G4 / 64, (BSZ * TT) / 64), 256>>>(x, Wx, b);

    for (int t = 0; t < TT; t++) {
        k_phaseA<<<dim3(G4 / 64, BSZ / 64), 256>>>(Rh, t);
        k_cell<<<(nElem + 511) / 512, 512>>>();
        k_phaseB<<<dim3(HH / 64, BSZ / 64, 3), 256>>>(Po, Pf, Pi, out, (t == TT - 1) ? 1 : 0);
    }
}